// round 13
// baseline (speedup 1.0000x reference)
#include <cuda_runtime.h>
#include <cuda_fp16.h>
#include <cstdint>

// ---------------- problem constants ----------------
#define N_NODES 50000
#define N_EDGES 500000
#define FD      128
#define KDIM    384
#define NOUT    256
#define TILE_G  32
#define NT_G    (N_EDGES / TILE_G)            // 15625
#define NGROUP  4
#define NODE_BLOCKS ((N_NODES + 7) / 8)       // 6250
#define PQ_TILES ((N_NODES + 31) / 32)        // 1563

// ---------------- wt global layout ----------------
#define W12_BYTES 131072     // 2 K-blocks x [512 rows x 128B]
#define W3_BYTES  65536      // 2 K-blocks x [256 rows x 128B]

// ---------------- edge-kernel smem ----------------
#define B_OFF     0                         // W3' resident, 65536
#define A_OFF     65536                     // 4 groups x 2 x 4096 (ea chunks)
#define A_BUF_G   4096
#define A_G_STRIDE (2 * A_BUF_G)
#define PQ_OFF    98304                     // 4 groups x 32768 (P 16K + Q 16K)
#define PQ_G_STRIDE 32768
#define IDX_OFF   229376                    // per group src[32]+dst[32]
#define PSUM_OFF  230400
#define SMEM_TOTAL 231424                   // <= 232448

// ---------------- pq-kernel smem ----------------
#define PQ_SMEM   (W12_BYTES + 2 * 4096)    // 139264

// ---------------- device scratch ----------------
__device__ __align__(256) __half        g_xn16[(size_t)N_NODES * FD];
__device__ __align__(256) __half        g_pq[(size_t)N_NODES * 512];   // [P(256)|Q(256)] permuted
__device__ __align__(256) unsigned char g_wt16[W12_BYTES + W3_BYTES];

// ---------------- ptx helpers ----------------
__device__ __forceinline__ uint32_t smem_u32(const void* p) {
    uint32_t a;
    asm("{ .reg .u64 t; cvta.to.shared.u64 t, %1; cvt.u32.u64 %0, t; }" : "=r"(a) : "l"(p));
    return a;
}
__device__ __forceinline__ void cpa16(uint32_t s, const void* g) {
    asm volatile("cp.async.cg.shared.global [%0], [%1], 16;" :: "r"(s), "l"(g));
}
#define CP_COMMIT() asm volatile("cp.async.commit_group;" ::: "memory")
#define CP_WAIT0()  asm volatile("cp.async.wait_group 0;" ::: "memory")
#define GBAR(g)     asm volatile("bar.sync %0, 128;" :: "r"((g) + 1) : "memory")

__device__ __forceinline__ void ldsm4(uint32_t* r, uint32_t addr) {
    asm volatile("ldmatrix.sync.aligned.m8n8.x4.shared.b16 {%0,%1,%2,%3}, [%4];"
                 : "=r"(r[0]), "=r"(r[1]), "=r"(r[2]), "=r"(r[3]) : "r"(addr));
}
__device__ __forceinline__ void mma16816(float* c, const uint32_t* a, uint32_t b0, uint32_t b1) {
    asm volatile("mma.sync.aligned.m16n8k16.row.col.f32.f16.f16.f32 "
                 "{%0,%1,%2,%3}, {%4,%5,%6,%7}, {%8,%9}, {%0,%1,%2,%3};"
                 : "+f"(c[0]), "+f"(c[1]), "+f"(c[2]), "+f"(c[3])
                 : "r"(a[0]), "r"(a[1]), "r"(a[2]), "r"(a[3]), "r"(b0), "r"(b1));
}
__device__ __forceinline__ void sts16(uint32_t addr, uint4 v) {
    asm volatile("st.shared.v4.b32 [%0], {%1,%2,%3,%4};"
                 :: "r"(addr), "r"(v.x), "r"(v.y), "r"(v.z), "r"(v.w) : "memory");
}
__device__ __forceinline__ float lds_h2x(uint32_t addr, float* hi) {
    uint32_t ru;
    asm volatile("ld.shared.b32 %0, [%1];" : "=r"(ru) : "r"(addr));
    float2 f = __half22float2(*(__half2*)&ru);
    *hi = f.y;
    return f.x;
}
__device__ __forceinline__ uint4 pack8h(float4 a, float4 b) {
    union { __half2 h[4]; uint4 u; } o;
    o.h[0] = __floats2half2_rn(a.x, a.y);
    o.h[1] = __floats2half2_rn(a.z, a.w);
    o.h[2] = __floats2half2_rn(b.x, b.y);
    o.h[3] = __floats2half2_rn(b.z, b.w);
    return o.u;
}
// streaming (evict-first) global load/store — protect g_pq residency in L2
__device__ __forceinline__ float4 ldg_cs4(const float* p) {
    float4 v;
    asm volatile("ld.global.cs.v4.f32 {%0,%1,%2,%3}, [%4];"
                 : "=f"(v.x), "=f"(v.y), "=f"(v.z), "=f"(v.w) : "l"(p));
    return v;
}
__device__ __forceinline__ void stg_cs2(float* p, float2 v) {
    asm volatile("st.global.cs.v2.f32 [%0], {%1,%2};" :: "l"(p), "f"(v.x), "f"(v.y) : "memory");
}

// column permutation: permuted col c (0..255) -> original W column
__device__ __forceinline__ int perm_col(int c) {
    const int strip = c >> 6, j = c & 63;
    const int f = strip * 32 + (j & 31);
    return (j < 32) ? f : (128 + f);
}

// =====================================================================
// prep: node LayerNorm -> f16 ; W -> W12' (K 0:256) + W3' (K 256:384)
// =====================================================================
__global__ void prep_kernel(const float* __restrict__ x, const float* __restrict__ gma,
                            const float* __restrict__ bta, const float* __restrict__ W) {
    if (blockIdx.x < NODE_BLOCKS) {
        const int wid = threadIdx.x >> 5, lane = threadIdx.x & 31;
        const int node = blockIdx.x * 8 + wid;
        if (node >= N_NODES) return;
        float4 v = *(const float4*)(x + (size_t)node * FD + lane * 4);
        float s = v.x + v.y + v.z + v.w;
        float q = v.x * v.x + v.y * v.y + v.z * v.z + v.w * v.w;
#pragma unroll
        for (int o = 16; o; o >>= 1) {
            s += __shfl_xor_sync(~0u, s, o);
            q += __shfl_xor_sync(~0u, q, o);
        }
        const float mu = s * (1.f / FD), var = q * (1.f / FD) - mu * mu;
        const float rs = rsqrtf(var + 1e-5f);
        float4 g = *(const float4*)(gma + lane * 4);
        float4 b = *(const float4*)(bta + lane * 4);
        union { __half2 h[2]; uint2 u; } o;
        o.h[0] = __floats2half2_rn((v.x - mu) * rs * g.x + b.x, (v.y - mu) * rs * g.y + b.y);
        o.h[1] = __floats2half2_rn((v.z - mu) * rs * g.z + b.z, (v.w - mu) * rs * g.w + b.w);
        *(uint2*)(g_xn16 + (size_t)node * FD + lane * 4) = o.u;
    } else if (blockIdx.x < NODE_BLOCKS + 512) {
        const int c = blockIdx.x - NODE_BLOCKS;
        const int t = threadIdx.x;
        if (t >= 16) return;
        const int half_sel = c >> 8;
        const int src_n = perm_col(c & 255);
        const int k0 = t * 8;
        const int kb = k0 >> 6, kl = k0 & 63;
        union { __half h[8]; uint4 u; } pk;
#pragma unroll
        for (int i = 0; i < 8; i++)
            pk.h[i] = __float2half_rn(W[(half_sel * 128 + k0 + i) * NOUT + src_n]);
        const uint32_t phys = kb * 65536 + c * 128 + ((((kl >> 3) ^ (c & 7))) << 4);
        *(uint4*)(g_wt16 + phys) = pk.u;
    } else {
        const int c = blockIdx.x - NODE_BLOCKS - 512;
        const int t = threadIdx.x;
        if (t >= 16) return;
        const int src_n = perm_col(c);
        const int k0 = t * 8;
        const int kb = k0 >> 6, kl = k0 & 63;
        union { __half h[8]; uint4 u; } pk;
#pragma unroll
        for (int i = 0; i < 8; i++)
            pk.h[i] = __float2half_rn(W[(256 + k0 + i) * NOUT + src_n]);
        const uint32_t phys = W12_BYTES + kb * 32768 + c * 128 + ((((kl >> 3) ^ (c & 7))) << 4);
        *(uint4*)(g_wt16 + phys) = pk.u;
    }
}

// =====================================================================
// pq_kernel: g_pq[node] = [xn@W1 | xn@W2] (f16, permuted cols)
// =====================================================================
__global__ void __launch_bounds__(256, 1)
pq_kernel() {
    extern __shared__ char smem[];
    const uint32_t sm_u = smem_u32(smem);
    const uint32_t bB = sm_u;
    const uint32_t bA = sm_u + W12_BYTES;

    const int tid = threadIdx.x;
    const int w = tid >> 5, lane = tid & 31;
    const int row8 = tid >> 3, q8 = tid & 7;
    const int lq = lane & 3, lr = lane >> 2;

    {
        const uint4* src = (const uint4*)g_wt16;
        uint4* dst = (uint4*)smem;
        for (int i = tid; i < W12_BYTES / 16; i += 256) dst[i] = src[i];
    }

    const int li = lane & 7, lgrp = lane >> 3;
    uint32_t a_off[2]; int a_r7[2];
#pragma unroll
    for (int s = 0; s < 2; s++) {
        const int row = s * 16 + li + (lgrp & 1) * 8;
        a_off[s] = row * 128;
        a_r7[s] = row & 7;
    }
    const int a_qb = lgrp >> 1;
    uint32_t b_off[4]; int b_r7[4];
#pragma unroll
    for (int j = 0; j < 4; j++) {
        const int rn = w * 64 + j * 16 + li + (lgrp >> 1) * 8;
        b_off[j] = rn * 128;
        b_r7[j] = rn & 7;
    }
    const int b_qb = lgrp & 1;

    const uint32_t d_off = row8 * 128 + ((q8 ^ (row8 & 7)) << 4);

    __syncthreads();

    {
        const int nb = blockIdx.x * TILE_G;
        const int node = min(nb + row8, N_NODES - 1);
        const char* gp = (const char*)(g_xn16 + (size_t)node * FD) + q8 * 16;
        cpa16(bA + d_off, gp);
        cpa16(bA + 4096 + d_off, gp + 128);
        CP_COMMIT();
    }

    for (int tt = blockIdx.x; tt < PQ_TILES; tt += gridDim.x) {
        const int nb = tt * TILE_G;
        float acc[2][8][4];
#pragma unroll
        for (int s = 0; s < 2; s++)
#pragma unroll
            for (int n = 0; n < 8; n++)
#pragma unroll
                for (int i = 0; i < 4; i++) acc[s][n][i] = 0.f;

        CP_WAIT0();
        __syncthreads();

#pragma unroll
        for (int c = 0; c < 2; c++) {
            const uint32_t abuf = bA + c * 4096;
            const uint32_t bblk = bB + c * 65536;
#pragma unroll
            for (int ks = 0; ks < 4; ks++) {
                uint32_t A[2][4];
#pragma unroll
                for (int s = 0; s < 2; s++)
                    ldsm4(A[s], abuf + a_off[s] + ((((2 * ks + a_qb) ^ a_r7[s])) << 4));
                uint32_t Bv[4][4];
#pragma unroll
                for (int j = 0; j < 4; j++)
                    ldsm4(Bv[j], bblk + b_off[j] + ((((2 * ks + b_qb) ^ b_r7[j])) << 4));
#pragma unroll
                for (int s = 0; s < 2; s++)
#pragma unroll
                    for (int j = 0; j < 4; j++) {
                        mma16816(acc[s][2 * j],     A[s], Bv[j][0], Bv[j][1]);
                        mma16816(acc[s][2 * j + 1], A[s], Bv[j][2], Bv[j][3]);
                    }
            }
        }
        __syncthreads();

        if (tt + (int)gridDim.x < PQ_TILES) {
            const int nbn = (tt + gridDim.x) * TILE_G;
            const int node = min(nbn + row8, N_NODES - 1);
            const char* gp = (const char*)(g_xn16 + (size_t)node * FD) + q8 * 16;
            cpa16(bA + d_off, gp);
            cpa16(bA + 4096 + d_off, gp + 128);
            CP_COMMIT();
        }

#pragma unroll
        for (int s = 0; s < 2; s++)
#pragma unroll
            for (int rh = 0; rh < 2; rh++) {
                const int node = nb + s * 16 + rh * 8 + lr;
                if (node < N_NODES) {
#pragma unroll
                    for (int n = 0; n < 8; n++) {
                        const int col = w * 64 + n * 8 + lq * 2;
                        __half2 h = __floats2half2_rn(acc[s][n][rh * 2], acc[s][n][rh * 2 + 1]);
                        *(__half2*)(g_pq + (size_t)node * 512 + col) = h;
                    }
                }
            }
    }
}

// =====================================================================
// edge kernel: K=128 GEMM (ea@W3) + P[src]+Q[dst] gather + epilogue
// =====================================================================
__global__ void __launch_bounds__(512, 1)
edge_kernel(const int* __restrict__ ei, const float* __restrict__ ea,
            const float* __restrict__ bias, const float* __restrict__ eg,
            const float* __restrict__ eb, float* __restrict__ out) {
    extern __shared__ char smem[];
    const uint32_t sm_u = smem_u32(smem);
    const uint32_t bB = sm_u + B_OFF;

    const int tid  = threadIdx.x;
    const int g    = tid >> 7;
    const int ltid = tid & 127;
    const int wc   = ltid >> 5;
    const int lane = ltid & 31;
    const int row4 = ltid >> 2, q4 = ltid & 3;
    const int r7 = row4 & 7;
    const int lq = lane & 3, lr = lane >> 2;

    const uint32_t bA = sm_u + A_OFF + g * A_G_STRIDE;
    const uint32_t Ps = sm_u + PQ_OFF + g * PQ_G_STRIDE;
    const uint32_t Qs = Ps + 16384;
    int*   s_src = (int*)(smem + IDX_OFF) + g * 64;
    int*   s_dst = s_src + 32;
    float* psum  = (float*)(smem + PSUM_OFF) + g * 64;

    {
        const uint4* src = (const uint4*)(g_wt16 + W12_BYTES);
        uint4* dst = (uint4*)(smem + B_OFF);
        for (int i = tid; i < W3_BYTES / 16; i += 512) dst[i] = src[i];
    }

    const int li = lane & 7, lgrp = lane >> 3;
    uint32_t a_off[2]; int a_r7[2];
#pragma unroll
    for (int s = 0; s < 2; s++) {
        const int row = s * 16 + li + (lgrp & 1) * 8;
        a_off[s] = row * 128;
        a_r7[s] = row & 7;
    }
    const int a_qb = lgrp >> 1;
    uint32_t b_off[4]; int b_r7[4];
#pragma unroll
    for (int j = 0; j < 4; j++) {
        const int rn = wc * 64 + j * 16 + li + (lgrp >> 1) * 8;
        b_off[j] = rn * 128;
        b_r7[j] = rn & 7;
    }
    const int b_qb = lgrp & 1;

    const uint32_t d_off0 = row4 * 128 + (((2 * q4) ^ r7) << 4);
    const uint32_t d_off1 = row4 * 128 + (((2 * q4 + 1) ^ r7) << 4);
    const uint32_t res_base = bA + (wc >> 1) * A_BUF_G;

    __syncthreads();

    const int t0 = blockIdx.x * NGROUP + g;
    const int tstride = gridDim.x * NGROUP;

    float acc[2][8][4];
    float4 ea_lo[4], ea_hi[4];

    auto MMAPH = [&](int c) {
        const uint32_t abuf = bA + c * A_BUF_G;
        const uint32_t bblk = bB + c * 32768;
#pragma unroll
        for (int ks = 0; ks < 4; ks++) {
            uint32_t A[2][4];
#pragma unroll
            for (int s = 0; s < 2; s++)
                ldsm4(A[s], abuf + a_off[s] + ((((2 * ks + a_qb) ^ a_r7[s])) << 4));
            uint32_t Bv[4][4];
#pragma unroll
            for (int j = 0; j < 4; j++)
                ldsm4(Bv[j], bblk + b_off[j] + ((((2 * ks + b_qb) ^ b_r7[j])) << 4));
#pragma unroll
            for (int s = 0; s < 2; s++)
#pragma unroll
                for (int j = 0; j < 4; j++) {
                    mma16816(acc[s][2 * j],     A[s], Bv[j][0], Bv[j][1]);
                    mma16816(acc[s][2 * j + 1], A[s], Bv[j][2], Bv[j][3]);
                }
        }
    };
    // streaming (evict-first) ea load: feats [off, off+64)
    auto LDG_EA = [&](int base, int off, float4* d) {
        const float* p = ea + (size_t)base * FD + off + q4 * 16;
        d[0] = ldg_cs4(p);
        d[1] = ldg_cs4(p + 4);
        d[2] = ldg_cs4(p + 8);
        d[3] = ldg_cs4(p + 12);
    };
    auto PQ_GATHER = [&]() {
        const int ns = s_src[row4], nd = s_dst[row4];
        const char* gps = (const char*)g_pq + (size_t)ns * 1024;
        const char* gpq = (const char*)g_pq + (size_t)nd * 1024 + 512;
        const uint32_t rbase_p = Ps + row4 * 512;
        const uint32_t rbase_q = Qs + row4 * 512;
#pragma unroll
        for (int k = 0; k < 8; k++) {
            const uint32_t u = q4 * 8 + k;
            const uint32_t sw = ((u ^ (uint32_t)r7) << 4);
            cpa16(rbase_p + sw, gps + u * 16);
            cpa16(rbase_q + sw, gpq + u * 16);
        }
        CP_COMMIT();
    };

    // ---- prologue ----
    if (t0 < NT_G) {
        const int tb0 = t0 * TILE_G;
        if (ltid < 32)      s_src[ltid] = ei[tb0 + ltid];
        else if (ltid < 64) s_dst[ltid - 32] = ei[N_EDGES + tb0 + ltid - 32];
    }
    GBAR(g);
    if (t0 < NT_G) {
        LDG_EA(t0 * TILE_G + row4, 0, ea_lo);
        PQ_GATHER();
    }

    for (int t = t0; t < NT_G; t += tstride) {
        const int tb = t * TILE_G;
        const int er = tb + row4;
        const bool more = (t + tstride) < NT_G;

#pragma unroll
        for (int s = 0; s < 2; s++)
#pragma unroll
            for (int n = 0; n < 8; n++)
#pragma unroll
                for (int i = 0; i < 4; i++) acc[s][n][i] = 0.f;

        // ---- c0: ea feats 0-63 ----
        sts16(bA + d_off0, pack8h(ea_lo[0], ea_lo[1]));
        sts16(bA + d_off1, pack8h(ea_lo[2], ea_lo[3]));
        GBAR(g);
        if (ltid >= 64) psum[ltid - 64] = 0.f;
        if (more) {
            const int tbn = (t + tstride) * TILE_G;
            if (ltid < 32)      s_src[ltid] = ei[tbn + ltid];
            else if (ltid < 64) s_dst[ltid - 32] = ei[N_EDGES + tbn + ltid - 32];
        }
        LDG_EA(er, 64, ea_hi);   // feats 64-127 (overlaps MMA 0)
        MMAPH(0);

        // ---- c1: ea feats 64-127 ----
        sts16(bA + A_BUF_G + d_off0, pack8h(ea_hi[0], ea_hi[1]));
        sts16(bA + A_BUF_G + d_off1, pack8h(ea_hi[2], ea_hi[3]));
        GBAR(g);
        MMAPH(1);

        // ---- PQ landed; epilogue part 1 ----
        CP_WAIT0();
        GBAR(g);
        {
            float srs[4], qrs[4];
#pragma unroll
            for (int ri = 0; ri < 4; ri++) { srs[ri] = 0.f; qrs[ri] = 0.f; }

#pragma unroll
            for (int n = 0; n < 4; n++) {
                const int f = wc * 32 + n * 8 + lq * 2;
                const float2 bd = __ldg((const float2*)(bias + f));
                const float2 bg = __ldg((const float2*)(bias + 128 + f));
                const uint32_t colb_r = (wc & 1) * 64 + n * 16 + lq * 4;
                const uint32_t unit_r = colb_r >> 4;
                const uint32_t colb_p = wc * 128 + n * 16 + lq * 4;
                const uint32_t unit_p = colb_p >> 4;
#pragma unroll
                for (int s = 0; s < 2; s++)
#pragma unroll
                    for (int rh = 0; rh < 2; rh++) {
                        const int ri = s * 2 + rh;
                        const int row = s * 16 + rh * 8 + lr;
                        const uint32_t rx = (uint32_t)(row & 7);
                        float r1, p1, p3, q1, q3;
                        const float r0 = lds_h2x(res_base + row * 128 + ((unit_r ^ rx) << 4) + (colb_r & 15), &r1);
                        const uint32_t prow = Ps + row * 512;
                        const uint32_t qrow = Qs + row * 512;
                        const float p0 = lds_h2x(prow + ((unit_p ^ rx) << 4) + (colb_p & 15), &p1);
                        const float p2 = lds_h2x(prow + (((unit_p + 4) ^ rx) << 4) + (colb_p & 15), &p3);
                        const float q0 = lds_h2x(qrow + ((unit_p ^ rx) << 4) + (colb_p & 15), &q1);
                        const float q2 = lds_h2x(qrow + (((unit_p + 4) ^ rx) << 4) + (colb_p & 15), &q3);
                        float d0 = fmaxf(acc[s][n][rh * 2 + 0] + p0 + q0 + bd.x, 0.f);
                        float d1 = fmaxf(acc[s][n][rh * 2 + 1] + p1 + q1 + bd.y, 0.f);
                        float g0 = fmaxf(acc[s][n + 4][rh * 2 + 0] + p2 + q2 + bg.x, 0.f);
                        float g1 = fmaxf(acc[s][n + 4][rh * 2 + 1] + p3 + q3 + bg.y, 0.f);
                        float s0 = __frcp_rn(1.f + __expf(-g0));
                        float s1 = __frcp_rn(1.f + __expf(-g1));
                        float v0 = fmaf(d0, s0, r0);
                        float v1 = fmaf(d1, s1, r1);
                        acc[s][n][rh * 2 + 0] = v0;
                        acc[s][n][rh * 2 + 1] = v1;
                        srs[ri] += v0 + v1;
                        qrs[ri] = fmaf(v0, v0, fmaf(v1, v1, qrs[ri]));
                    }
            }
#pragma unroll
            for (int ri = 0; ri < 4; ri++) {
                float s_ = srs[ri], q_ = qrs[ri];
                s_ += __shfl_xor_sync(~0u, s_, 1);
                q_ += __shfl_xor_sync(~0u, q_, 1);
                s_ += __shfl_xor_sync(~0u, s_, 2);
                q_ += __shfl_xor_sync(~0u, q_, 2);
                if (lq == 0) {
                    const int row = (ri >> 1) * 16 + (ri & 1) * 8 + lr;
                    atomicAdd(&psum[row * 2],     s_);
                    atomicAdd(&psum[row * 2 + 1], q_);
                }
            }
        }
        GBAR(g);

        // ---- overlap next tile's loads with part 2 ----
        if (more) {
            LDG_EA((t + tstride) * TILE_G + row4, 0, ea_lo);
            PQ_GATHER();
        }

        // ---- epilogue part 2: LayerNorm + store (streaming) ----
        {
#pragma unroll
            for (int s = 0; s < 2; s++)
#pragma unroll
                for (int rh = 0; rh < 2; rh++) {
                    const int row = s * 16 + rh * 8 + lr;
                    const int e = tb + row;
                    const float2 p = *(const float2*)(psum + row * 2);
                    const float mu = p.x * (1.f / FD);
                    const float var = p.y * (1.f / FD) - mu * mu;
                    const float rs = rsqrtf(var + 1e-5f);
#pragma unroll
                    for (int n = 0; n < 4; n++) {
                        const int f = wc * 32 + n * 8 + lq * 2;
                        const float2 gg = __ldg((const float2*)(eg + f));
                        const float2 bb = __ldg((const float2*)(eb + f));
                        float2 o;
                        o.x = (acc[s][n][rh * 2 + 0] - mu) * rs * gg.x + bb.x;
                        o.y = (acc[s][n][rh * 2 + 1] - mu) * rs * gg.y + bb.y;
                        stg_cs2(out + (size_t)e * FD + f, o);
                    }
                }
        }
    }
}

// =====================================================================
// launch
// =====================================================================
extern "C" void kernel_launch(void* const* d_in, const int* in_sizes, int n_in,
                              void* d_out, int out_size) {
    const float* x  = (const float*)d_in[0];
    const int*   ei = (const int*)d_in[1];
    const float* ea = (const float*)d_in[2];
    const float* W  = (const float*)d_in[3];
    const float* b  = (const float*)d_in[4];
    const float* ng = (const float*)d_in[5];
    const float* nb = (const float*)d_in[6];
    const float* eg = (const float*)d_in[7];
    const float* eb = (const float*)d_in[8];
    float* out = (float*)d_out;

    int nsm = 148;
    cudaDeviceGetAttribute(&nsm, cudaDevAttrMultiProcessorCount, 0);

    prep_kernel<<<NODE_BLOCKS + 512 + 256, 256>>>(x, ng, nb, W);

    cudaFuncSetAttribute(pq_kernel, cudaFuncAttributeMaxDynamicSharedMemorySize, PQ_SMEM);
    pq_kernel<<<nsm, 256, PQ_SMEM>>>();

    cudaFuncSetAttribute(edge_kernel, cudaFuncAttributeMaxDynamicSharedMemorySize, SMEM_TOTAL);
    edge_kernel<<<nsm, 512, SMEM_TOTAL>>>(ei, ea, b, eg, eb, out);
}

// round 14
// speedup vs baseline: 1.0057x; 1.0057x over previous
#include <cuda_runtime.h>
#include <cuda_fp16.h>
#include <cstdint>

// ---------------- problem constants ----------------
#define N_NODES 50000
#define N_EDGES 500000
#define FD      128
#define KDIM    384
#define NOUT    256
#define TILE_G  32
#define NT_G    (N_EDGES / TILE_G)            // 15625
#define NGROUP  4
#define NODE_BLOCKS ((N_NODES + 7) / 8)       // 6250
#define PQ_TILES ((N_NODES + 31) / 32)        // 1563

// ---------------- wt global layout ----------------
#define W12_BYTES 131072     // 2 K-blocks x [512 rows x 128B]
#define W3_BYTES  65536      // 2 K-blocks x [256 rows x 128B]

// ---------------- edge-kernel smem ----------------
#define B_OFF     0                         // W3' resident, 65536
#define A_OFF     65536                     // 4 groups x 2 x 4096 (ea chunks)
#define A_BUF_G   4096
#define A_G_STRIDE (2 * A_BUF_G)
#define PQ_OFF    98304                     // 4 groups x 32768 (P 16K + Q 16K)
#define PQ_G_STRIDE 32768
#define IDX_OFF   229376                    // per group src[32]+dst[32]
#define PSUM_OFF  230400
#define SMEM_TOTAL 231424                   // <= 232448

// ---------------- pq-kernel smem ----------------
#define PQ_SMEM   (W12_BYTES + 2 * 4096)    // 139264

// ---------------- device scratch ----------------
__device__ __align__(256) __half        g_xn16[(size_t)N_NODES * FD];
__device__ __align__(256) __half        g_pq[(size_t)N_NODES * 512];   // [P(256)|Q(256)] permuted
__device__ __align__(256) unsigned char g_wt16[W12_BYTES + W3_BYTES];

// ---------------- ptx helpers ----------------
__device__ __forceinline__ uint32_t smem_u32(const void* p) {
    uint32_t a;
    asm("{ .reg .u64 t; cvta.to.shared.u64 t, %1; cvt.u32.u64 %0, t; }" : "=r"(a) : "l"(p));
    return a;
}
__device__ __forceinline__ void cpa16(uint32_t s, const void* g) {
    asm volatile("cp.async.cg.shared.global [%0], [%1], 16;" :: "r"(s), "l"(g));
}
#define CP_COMMIT() asm volatile("cp.async.commit_group;" ::: "memory")
#define CP_WAIT0()  asm volatile("cp.async.wait_group 0;" ::: "memory")
#define GBAR(g)     asm volatile("bar.sync %0, 128;" :: "r"((g) + 1) : "memory")

__device__ __forceinline__ void ldsm4(uint32_t* r, uint32_t addr) {
    asm volatile("ldmatrix.sync.aligned.m8n8.x4.shared.b16 {%0,%1,%2,%3}, [%4];"
                 : "=r"(r[0]), "=r"(r[1]), "=r"(r[2]), "=r"(r[3]) : "r"(addr));
}
__device__ __forceinline__ void mma16816(float* c, const uint32_t* a, uint32_t b0, uint32_t b1) {
    asm volatile("mma.sync.aligned.m16n8k16.row.col.f32.f16.f16.f32 "
                 "{%0,%1,%2,%3}, {%4,%5,%6,%7}, {%8,%9}, {%0,%1,%2,%3};"
                 : "+f"(c[0]), "+f"(c[1]), "+f"(c[2]), "+f"(c[3])
                 : "r"(a[0]), "r"(a[1]), "r"(a[2]), "r"(a[3]), "r"(b0), "r"(b1));
}
__device__ __forceinline__ void sts16(uint32_t addr, uint4 v) {
    asm volatile("st.shared.v4.b32 [%0], {%1,%2,%3,%4};"
                 :: "r"(addr), "r"(v.x), "r"(v.y), "r"(v.z), "r"(v.w) : "memory");
}
__device__ __forceinline__ float lds_h2x(uint32_t addr, float* hi) {
    uint32_t ru;
    asm volatile("ld.shared.b32 %0, [%1];" : "=r"(ru) : "r"(addr));
    float2 f = __half22float2(*(__half2*)&ru);
    *hi = f.y;
    return f.x;
}
__device__ __forceinline__ uint4 pack8h(float4 a, float4 b) {
    union { __half2 h[4]; uint4 u; } o;
    o.h[0] = __floats2half2_rn(a.x, a.y);
    o.h[1] = __floats2half2_rn(a.z, a.w);
    o.h[2] = __floats2half2_rn(b.x, b.y);
    o.h[3] = __floats2half2_rn(b.z, b.w);
    return o.u;
}
// streaming (evict-first) global load/store — protect g_pq residency in L2
__device__ __forceinline__ float4 ldg_cs4(const float* p) {
    float4 v;
    asm volatile("ld.global.cs.v4.f32 {%0,%1,%2,%3}, [%4];"
                 : "=f"(v.x), "=f"(v.y), "=f"(v.z), "=f"(v.w) : "l"(p));
    return v;
}
__device__ __forceinline__ void stg_cs2(float* p, float2 v) {
    asm volatile("st.global.cs.v2.f32 [%0], {%1,%2};" :: "l"(p), "f"(v.x), "f"(v.y) : "memory");
}

// column permutation: permuted col c (0..255) -> original W column
__device__ __forceinline__ int perm_col(int c) {
    const int strip = c >> 6, j = c & 63;
    const int f = strip * 32 + (j & 31);
    return (j < 32) ? f : (128 + f);
}

// =====================================================================
// prep: node LayerNorm -> f16 ; W -> W12' (K 0:256) + W3' (K 256:384)
// =====================================================================
__global__ void prep_kernel(const float* __restrict__ x, const float* __restrict__ gma,
                            const float* __restrict__ bta, const float* __restrict__ W) {
    if (blockIdx.x < NODE_BLOCKS) {
        const int wid = threadIdx.x >> 5, lane = threadIdx.x & 31;
        const int node = blockIdx.x * 8 + wid;
        if (node >= N_NODES) return;
        float4 v = *(const float4*)(x + (size_t)node * FD + lane * 4);
        float s = v.x + v.y + v.z + v.w;
        float q = v.x * v.x + v.y * v.y + v.z * v.z + v.w * v.w;
#pragma unroll
        for (int o = 16; o; o >>= 1) {
            s += __shfl_xor_sync(~0u, s, o);
            q += __shfl_xor_sync(~0u, q, o);
        }
        const float mu = s * (1.f / FD), var = q * (1.f / FD) - mu * mu;
        const float rs = rsqrtf(var + 1e-5f);
        float4 g = *(const float4*)(gma + lane * 4);
        float4 b = *(const float4*)(bta + lane * 4);
        union { __half2 h[2]; uint2 u; } o;
        o.h[0] = __floats2half2_rn((v.x - mu) * rs * g.x + b.x, (v.y - mu) * rs * g.y + b.y);
        o.h[1] = __floats2half2_rn((v.z - mu) * rs * g.z + b.z, (v.w - mu) * rs * g.w + b.w);
        *(uint2*)(g_xn16 + (size_t)node * FD + lane * 4) = o.u;
    } else if (blockIdx.x < NODE_BLOCKS + 512) {
        const int c = blockIdx.x - NODE_BLOCKS;
        const int t = threadIdx.x;
        if (t >= 16) return;
        const int half_sel = c >> 8;
        const int src_n = perm_col(c & 255);
        const int k0 = t * 8;
        const int kb = k0 >> 6, kl = k0 & 63;
        union { __half h[8]; uint4 u; } pk;
#pragma unroll
        for (int i = 0; i < 8; i++)
            pk.h[i] = __float2half_rn(W[(half_sel * 128 + k0 + i) * NOUT + src_n]);
        const uint32_t phys = kb * 65536 + c * 128 + ((((kl >> 3) ^ (c & 7))) << 4);
        *(uint4*)(g_wt16 + phys) = pk.u;
    } else {
        const int c = blockIdx.x - NODE_BLOCKS - 512;
        const int t = threadIdx.x;
        if (t >= 16) return;
        const int src_n = perm_col(c);
        const int k0 = t * 8;
        const int kb = k0 >> 6, kl = k0 & 63;
        union { __half h[8]; uint4 u; } pk;
#pragma unroll
        for (int i = 0; i < 8; i++)
            pk.h[i] = __float2half_rn(W[(256 + k0 + i) * NOUT + src_n]);
        const uint32_t phys = W12_BYTES + kb * 32768 + c * 128 + ((((kl >> 3) ^ (c & 7))) << 4);
        *(uint4*)(g_wt16 + phys) = pk.u;
    }
}

// =====================================================================
// pq_kernel: g_pq[node] = [xn@W1 | xn@W2] (f16, permuted cols)
// =====================================================================
__global__ void __launch_bounds__(256, 1)
pq_kernel() {
    extern __shared__ char smem[];
    const uint32_t sm_u = smem_u32(smem);
    const uint32_t bB = sm_u;
    const uint32_t bA = sm_u + W12_BYTES;

    const int tid = threadIdx.x;
    const int w = tid >> 5, lane = tid & 31;
    const int row8 = tid >> 3, q8 = tid & 7;
    const int lq = lane & 3, lr = lane >> 2;

    {
        const uint4* src = (const uint4*)g_wt16;
        uint4* dst = (uint4*)smem;
        for (int i = tid; i < W12_BYTES / 16; i += 256) dst[i] = src[i];
    }

    const int li = lane & 7, lgrp = lane >> 3;
    uint32_t a_off[2]; int a_r7[2];
#pragma unroll
    for (int s = 0; s < 2; s++) {
        const int row = s * 16 + li + (lgrp & 1) * 8;
        a_off[s] = row * 128;
        a_r7[s] = row & 7;
    }
    const int a_qb = lgrp >> 1;
    uint32_t b_off[4]; int b_r7[4];
#pragma unroll
    for (int j = 0; j < 4; j++) {
        const int rn = w * 64 + j * 16 + li + (lgrp >> 1) * 8;
        b_off[j] = rn * 128;
        b_r7[j] = rn & 7;
    }
    const int b_qb = lgrp & 1;

    const uint32_t d_off = row8 * 128 + ((q8 ^ (row8 & 7)) << 4);

    __syncthreads();

    {
        const int nb = blockIdx.x * TILE_G;
        const int node = min(nb + row8, N_NODES - 1);
        const char* gp = (const char*)(g_xn16 + (size_t)node * FD) + q8 * 16;
        cpa16(bA + d_off, gp);
        cpa16(bA + 4096 + d_off, gp + 128);
        CP_COMMIT();
    }

    for (int tt = blockIdx.x; tt < PQ_TILES; tt += gridDim.x) {
        const int nb = tt * TILE_G;
        float acc[2][8][4];
#pragma unroll
        for (int s = 0; s < 2; s++)
#pragma unroll
            for (int n = 0; n < 8; n++)
#pragma unroll
                for (int i = 0; i < 4; i++) acc[s][n][i] = 0.f;

        CP_WAIT0();
        __syncthreads();

#pragma unroll
        for (int c = 0; c < 2; c++) {
            const uint32_t abuf = bA + c * 4096;
            const uint32_t bblk = bB + c * 65536;
#pragma unroll
            for (int ks = 0; ks < 4; ks++) {
                uint32_t A[2][4];
#pragma unroll
                for (int s = 0; s < 2; s++)
                    ldsm4(A[s], abuf + a_off[s] + ((((2 * ks + a_qb) ^ a_r7[s])) << 4));
                uint32_t Bv[4][4];
#pragma unroll
                for (int j = 0; j < 4; j++)
                    ldsm4(Bv[j], bblk + b_off[j] + ((((2 * ks + b_qb) ^ b_r7[j])) << 4));
#pragma unroll
                for (int s = 0; s < 2; s++)
#pragma unroll
                    for (int j = 0; j < 4; j++) {
                        mma16816(acc[s][2 * j],     A[s], Bv[j][0], Bv[j][1]);
                        mma16816(acc[s][2 * j + 1], A[s], Bv[j][2], Bv[j][3]);
                    }
            }
        }
        __syncthreads();

        if (tt + (int)gridDim.x < PQ_TILES) {
            const int nbn = (tt + gridDim.x) * TILE_G;
            const int node = min(nbn + row8, N_NODES - 1);
            const char* gp = (const char*)(g_xn16 + (size_t)node * FD) + q8 * 16;
            cpa16(bA + d_off, gp);
            cpa16(bA + 4096 + d_off, gp + 128);
            CP_COMMIT();
        }

#pragma unroll
        for (int s = 0; s < 2; s++)
#pragma unroll
            for (int rh = 0; rh < 2; rh++) {
                const int node = nb + s * 16 + rh * 8 + lr;
                if (node < N_NODES) {
#pragma unroll
                    for (int n = 0; n < 8; n++) {
                        const int col = w * 64 + n * 8 + lq * 2;
                        __half2 h = __floats2half2_rn(acc[s][n][rh * 2], acc[s][n][rh * 2 + 1]);
                        *(__half2*)(g_pq + (size_t)node * 512 + col) = h;
                    }
                }
            }
    }
}

// =====================================================================
// edge kernel: K=128 GEMM (ea@W3) + P[src]+Q[dst] gather + epilogue
// =====================================================================
__global__ void __launch_bounds__(512, 1)
edge_kernel(const int* __restrict__ ei, const float* __restrict__ ea,
            const float* __restrict__ bias, const float* __restrict__ eg,
            const float* __restrict__ eb, float* __restrict__ out) {
    extern __shared__ char smem[];
    const uint32_t sm_u = smem_u32(smem);
    const uint32_t bB = sm_u + B_OFF;

    const int tid  = threadIdx.x;
    const int g    = tid >> 7;
    const int ltid = tid & 127;
    const int wc   = ltid >> 5;
    const int lane = ltid & 31;
    const int row4 = ltid >> 2, q4 = ltid & 3;
    const int r7 = row4 & 7;
    const int lq = lane & 3, lr = lane >> 2;

    const uint32_t bA = sm_u + A_OFF + g * A_G_STRIDE;
    const uint32_t Ps = sm_u + PQ_OFF + g * PQ_G_STRIDE;
    const uint32_t Qs = Ps + 16384;
    int*   s_src = (int*)(smem + IDX_OFF) + g * 64;
    int*   s_dst = s_src + 32;
    float* psum  = (float*)(smem + PSUM_OFF) + g * 64;

    {
        const uint4* src = (const uint4*)(g_wt16 + W12_BYTES);
        uint4* dst = (uint4*)(smem + B_OFF);
        for (int i = tid; i < W3_BYTES / 16; i += 512) dst[i] = src[i];
    }

    const int li = lane & 7, lgrp = lane >> 3;
    uint32_t a_off[2]; int a_r7[2];
#pragma unroll
    for (int s = 0; s < 2; s++) {
        const int row = s * 16 + li + (lgrp & 1) * 8;
        a_off[s] = row * 128;
        a_r7[s] = row & 7;
    }
    const int a_qb = lgrp >> 1;
    uint32_t b_off[4]; int b_r7[4];
#pragma unroll
    for (int j = 0; j < 4; j++) {
        const int rn = wc * 64 + j * 16 + li + (lgrp >> 1) * 8;
        b_off[j] = rn * 128;
        b_r7[j] = rn & 7;
    }
    const int b_qb = lgrp & 1;

    const uint32_t d_off0 = row4 * 128 + (((2 * q4) ^ r7) << 4);
    const uint32_t d_off1 = row4 * 128 + (((2 * q4 + 1) ^ r7) << 4);
    const uint32_t res_base = bA + (wc >> 1) * A_BUF_G;

    __syncthreads();

    const int t0 = blockIdx.x * NGROUP + g;
    const int tstride = gridDim.x * NGROUP;

    float acc[2][8][4];
    float4 ea_lo[4], ea_hi[4];

    auto MMAPH = [&](int c) {
        const uint32_t abuf = bA + c * A_BUF_G;
        const uint32_t bblk = bB + c * 32768;
#pragma unroll
        for (int ks = 0; ks < 4; ks++) {
            uint32_t A[2][4];
#pragma unroll
            for (int s = 0; s < 2; s++)
                ldsm4(A[s], abuf + a_off[s] + ((((2 * ks + a_qb) ^ a_r7[s])) << 4));
            uint32_t Bv[4][4];
#pragma unroll
            for (int j = 0; j < 4; j++)
                ldsm4(Bv[j], bblk + b_off[j] + ((((2 * ks + b_qb) ^ b_r7[j])) << 4));
#pragma unroll
            for (int s = 0; s < 2; s++)
#pragma unroll
                for (int j = 0; j < 4; j++) {
                    mma16816(acc[s][2 * j],     A[s], Bv[j][0], Bv[j][1]);
                    mma16816(acc[s][2 * j + 1], A[s], Bv[j][2], Bv[j][3]);
                }
        }
    };
    // streaming (evict-first) ea load: feats [off, off+64)
    auto LDG_EA = [&](int base, int off, float4* d) {
        const float* p = ea + (size_t)base * FD + off + q4 * 16;
        d[0] = ldg_cs4(p);
        d[1] = ldg_cs4(p + 4);
        d[2] = ldg_cs4(p + 8);
        d[3] = ldg_cs4(p + 12);
    };
    auto PQ_GATHER = [&]() {
        const int ns = s_src[row4], nd = s_dst[row4];
        const char* gps = (const char*)g_pq + (size_t)ns * 1024;
        const char* gpq = (const char*)g_pq + (size_t)nd * 1024 + 512;
        const uint32_t rbase_p = Ps + row4 * 512;
        const uint32_t rbase_q = Qs + row4 * 512;
#pragma unroll
        for (int k = 0; k < 8; k++) {
            const uint32_t u = q4 * 8 + k;
            const uint32_t sw = ((u ^ (uint32_t)r7) << 4);
            cpa16(rbase_p + sw, gps + u * 16);
            cpa16(rbase_q + sw, gpq + u * 16);
        }
        CP_COMMIT();
    };

    // ---- prologue ----
    if (t0 < NT_G) {
        const int tb0 = t0 * TILE_G;
        if (ltid < 32)      s_src[ltid] = ei[tb0 + ltid];
        else if (ltid < 64) s_dst[ltid - 32] = ei[N_EDGES + tb0 + ltid - 32];
    }
    GBAR(g);
    if (t0 < NT_G) {
        LDG_EA(t0 * TILE_G + row4, 0, ea_lo);
        PQ_GATHER();
    }

    for (int t = t0; t < NT_G; t += tstride) {
        const int tb = t * TILE_G;
        const int er = tb + row4;
        const bool more = (t + tstride) < NT_G;

#pragma unroll
        for (int s = 0; s < 2; s++)
#pragma unroll
            for (int n = 0; n < 8; n++)
#pragma unroll
                for (int i = 0; i < 4; i++) acc[s][n][i] = 0.f;

        // ---- c0: ea feats 0-63 ----
        sts16(bA + d_off0, pack8h(ea_lo[0], ea_lo[1]));
        sts16(bA + d_off1, pack8h(ea_lo[2], ea_lo[3]));
        GBAR(g);
        if (ltid >= 64) psum[ltid - 64] = 0.f;
        if (more) {
            const int tbn = (t + tstride) * TILE_G;
            if (ltid < 32)      s_src[ltid] = ei[tbn + ltid];
            else if (ltid < 64) s_dst[ltid - 32] = ei[N_EDGES + tbn + ltid - 32];
        }
        LDG_EA(er, 64, ea_hi);   // feats 64-127 (overlaps MMA 0)
        MMAPH(0);

        // ---- c1: ea feats 64-127 ----
        sts16(bA + A_BUF_G + d_off0, pack8h(ea_hi[0], ea_hi[1]));
        sts16(bA + A_BUF_G + d_off1, pack8h(ea_hi[2], ea_hi[3]));
        GBAR(g);
        MMAPH(1);

        // ---- PQ landed; epilogue part 1 ----
        CP_WAIT0();
        GBAR(g);
        {
            float srs[4], qrs[4];
#pragma unroll
            for (int ri = 0; ri < 4; ri++) { srs[ri] = 0.f; qrs[ri] = 0.f; }

#pragma unroll
            for (int n = 0; n < 4; n++) {
                const int f = wc * 32 + n * 8 + lq * 2;
                const float2 bd = __ldg((const float2*)(bias + f));
                const float2 bg = __ldg((const float2*)(bias + 128 + f));
                const uint32_t colb_r = (wc & 1) * 64 + n * 16 + lq * 4;
                const uint32_t unit_r = colb_r >> 4;
                const uint32_t colb_p = wc * 128 + n * 16 + lq * 4;
                const uint32_t unit_p = colb_p >> 4;
#pragma unroll
                for (int s = 0; s < 2; s++)
#pragma unroll
                    for (int rh = 0; rh < 2; rh++) {
                        const int ri = s * 2 + rh;
                        const int row = s * 16 + rh * 8 + lr;
                        const uint32_t rx = (uint32_t)(row & 7);
                        float r1, p1, p3, q1, q3;
                        const float r0 = lds_h2x(res_base + row * 128 + ((unit_r ^ rx) << 4) + (colb_r & 15), &r1);
                        const uint32_t prow = Ps + row * 512;
                        const uint32_t qrow = Qs + row * 512;
                        const float p0 = lds_h2x(prow + ((unit_p ^ rx) << 4) + (colb_p & 15), &p1);
                        const float p2 = lds_h2x(prow + (((unit_p + 4) ^ rx) << 4) + (colb_p & 15), &p3);
                        const float q0 = lds_h2x(qrow + ((unit_p ^ rx) << 4) + (colb_p & 15), &q1);
                        const float q2 = lds_h2x(qrow + (((unit_p + 4) ^ rx) << 4) + (colb_p & 15), &q3);
                        float d0 = fmaxf(acc[s][n][rh * 2 + 0] + p0 + q0 + bd.x, 0.f);
                        float d1 = fmaxf(acc[s][n][rh * 2 + 1] + p1 + q1 + bd.y, 0.f);
                        float g0 = fmaxf(acc[s][n + 4][rh * 2 + 0] + p2 + q2 + bg.x, 0.f);
                        float g1 = fmaxf(acc[s][n + 4][rh * 2 + 1] + p3 + q3 + bg.y, 0.f);
                        float s0 = __frcp_rn(1.f + __expf(-g0));
                        float s1 = __frcp_rn(1.f + __expf(-g1));
                        float v0 = fmaf(d0, s0, r0);
                        float v1 = fmaf(d1, s1, r1);
                        acc[s][n][rh * 2 + 0] = v0;
                        acc[s][n][rh * 2 + 1] = v1;
                        srs[ri] += v0 + v1;
                        qrs[ri] = fmaf(v0, v0, fmaf(v1, v1, qrs[ri]));
                    }
            }
#pragma unroll
            for (int ri = 0; ri < 4; ri++) {
                float s_ = srs[ri], q_ = qrs[ri];
                s_ += __shfl_xor_sync(~0u, s_, 1);
                q_ += __shfl_xor_sync(~0u, q_, 1);
                s_ += __shfl_xor_sync(~0u, s_, 2);
                q_ += __shfl_xor_sync(~0u, q_, 2);
                if (lq == 0) {
                    const int row = (ri >> 1) * 16 + (ri & 1) * 8 + lr;
                    atomicAdd(&psum[row * 2],     s_);
                    atomicAdd(&psum[row * 2 + 1], q_);
                }
            }
        }
        GBAR(g);

        // ---- overlap next tile's loads with part 2 ----
        if (more) {
            LDG_EA((t + tstride) * TILE_G + row4, 0, ea_lo);
            PQ_GATHER();
        }

        // ---- epilogue part 2: LayerNorm + store (streaming) ----
        {
#pragma unroll
            for (int s = 0; s < 2; s++)
#pragma unroll
                for (int rh = 0; rh < 2; rh++) {
                    const int row = s * 16 + rh * 8 + lr;
                    const int e = tb + row;
                    const float2 p = *(const float2*)(psum + row * 2);
                    const float mu = p.x * (1.f / FD);
                    const float var = p.y * (1.f / FD) - mu * mu;
                    const float rs = rsqrtf(var + 1e-5f);
#pragma unroll
                    for (int n = 0; n < 4; n++) {
                        const int f = wc * 32 + n * 8 + lq * 2;
                        const float2 gg = __ldg((const float2*)(eg + f));
                        const float2 bb = __ldg((const float2*)(eb + f));
                        float2 o;
                        o.x = (acc[s][n][rh * 2 + 0] - mu) * rs * gg.x + bb.x;
                        o.y = (acc[s][n][rh * 2 + 1] - mu) * rs * gg.y + bb.y;
                        stg_cs2(out + (size_t)e * FD + f, o);
                    }
                }
        }
    }
}

// =====================================================================
// launch
// =====================================================================
extern "C" void kernel_launch(void* const* d_in, const int* in_sizes, int n_in,
                              void* d_out, int out_size) {
    const float* x  = (const float*)d_in[0];
    const int*   ei = (const int*)d_in[1];
    const float* ea = (const float*)d_in[2];
    const float* W  = (const float*)d_in[3];
    const float* b  = (const float*)d_in[4];
    const float* ng = (const float*)d_in[5];
    const float* nb = (const float*)d_in[6];
    const float* eg = (const float*)d_in[7];
    const float* eb = (const float*)d_in[8];
    float* out = (float*)d_out;

    int nsm = 148;
    cudaDeviceGetAttribute(&nsm, cudaDevAttrMultiProcessorCount, 0);

    prep_kernel<<<NODE_BLOCKS + 512 + 256, 256>>>(x, ng, nb, W);

    cudaFuncSetAttribute(pq_kernel, cudaFuncAttributeMaxDynamicSharedMemorySize, PQ_SMEM);
    pq_kernel<<<nsm, 256, PQ_SMEM>>>();

    cudaFuncSetAttribute(edge_kernel, cudaFuncAttributeMaxDynamicSharedMemorySize, SMEM_TOTAL);
    edge_kernel<<<nsm, 512, SMEM_TOTAL>>>(ei, ea, b, eg, eb, out);
}

// round 15
// speedup vs baseline: 1.1712x; 1.1646x over previous
#include <cuda_runtime.h>
#include <cuda_fp16.h>
#include <cstdint>

// ---------------- problem constants ----------------
#define N_NODES 50000
#define N_EDGES 500000
#define FD      128
#define KDIM    384
#define NOUT    256
#define TILE_G  32                            // edges per group tile
#define NT_G    (N_EDGES / TILE_G)            // 15625 (exact)
#define NGROUP  3                             // groups of 8 warps (256 thr)
#define NODE_BLOCKS ((N_NODES + 7) / 8)       // 6250

// ---------------- smem layout ----------------
#define B_OFF       0
#define B_BYTES     (6 * 32768)               // 6 K-blocks [256 n-rows x 64 halves], swizzled
#define A_OFF       B_BYTES                   // 196608
#define A_BUF_G     4096                      // one chunk [32 rows x 64 halves], swizzled
#define A_G_STRIDE  (2 * A_BUF_G)             // double buffer per group
#define IDX_OFF     (A_OFF + NGROUP * A_G_STRIDE)  // 221184
#define PSUM_OFF    (IDX_OFF + 1024)          // 222208
#define SMEM_TOTAL  (PSUM_OFF + 1024)         // 223232 <= 232448

// ---------------- device scratch ----------------
__device__ __align__(256) __half        g_xn16[(size_t)N_NODES * FD];
__device__ __align__(256) unsigned char g_wt16[B_BYTES];

// ---------------- ptx helpers ----------------
__device__ __forceinline__ uint32_t smem_u32(const void* p) {
    uint32_t a;
    asm("{ .reg .u64 t; cvta.to.shared.u64 t, %1; cvt.u32.u64 %0, t; }" : "=r"(a) : "l"(p));
    return a;
}
__device__ __forceinline__ void cpa16(uint32_t s, const void* g) {
    asm volatile("cp.async.cg.shared.global [%0], [%1], 16;" :: "r"(s), "l"(g));
}
#define CP_COMMIT() asm volatile("cp.async.commit_group;" ::: "memory")
#define CP_WAIT0()  asm volatile("cp.async.wait_group 0;" ::: "memory")
#define GBAR(g)     asm volatile("bar.sync %0, 256;" :: "r"((g) + 1) : "memory")

__device__ __forceinline__ void ldsm4(uint32_t* r, uint32_t addr) {
    asm volatile("ldmatrix.sync.aligned.m8n8.x4.shared.b16 {%0,%1,%2,%3}, [%4];"
                 : "=r"(r[0]), "=r"(r[1]), "=r"(r[2]), "=r"(r[3]) : "r"(addr));
}
__device__ __forceinline__ void mma16816(float* c, const uint32_t* a, uint32_t b0, uint32_t b1) {
    asm volatile("mma.sync.aligned.m16n8k16.row.col.f32.f16.f16.f32 "
                 "{%0,%1,%2,%3}, {%4,%5,%6,%7}, {%8,%9}, {%0,%1,%2,%3};"
                 : "+f"(c[0]), "+f"(c[1]), "+f"(c[2]), "+f"(c[3])
                 : "r"(a[0]), "r"(a[1]), "r"(a[2]), "r"(a[3]), "r"(b0), "r"(b1));
}
__device__ __forceinline__ void sts16(uint32_t addr, uint4 v) {
    asm volatile("st.shared.v4.b32 [%0], {%1,%2,%3,%4};"
                 :: "r"(addr), "r"(v.x), "r"(v.y), "r"(v.z), "r"(v.w) : "memory");
}
__device__ __forceinline__ uint4 pack8h(float4 a, float4 b) {
    union { __half2 h[4]; uint4 u; } o;
    o.h[0] = __floats2half2_rn(a.x, a.y);
    o.h[1] = __floats2half2_rn(a.z, a.w);
    o.h[2] = __floats2half2_rn(b.x, b.y);
    o.h[3] = __floats2half2_rn(b.z, b.w);
    return o.u;
}
// streaming (evict-first) loads/stores: keep g_xn16 L2-resident
__device__ __forceinline__ float4 ldg_cs4(const float* p) {
    float4 v;
    asm volatile("ld.global.cs.v4.f32 {%0,%1,%2,%3}, [%4];"
                 : "=f"(v.x), "=f"(v.y), "=f"(v.z), "=f"(v.w) : "l"(p));
    return v;
}
__device__ __forceinline__ void stg_cs2(float* p, float2 v) {
    asm volatile("st.global.cs.v2.f32 [%0], {%1,%2};" :: "l"(p), "f"(v.x), "f"(v.y) : "memory");
}

// =====================================================================
// prep: per-node LayerNorm -> f16, plus W convert/permute/swizzle
// =====================================================================
__global__ void prep_kernel(const float* __restrict__ x, const float* __restrict__ gma,
                            const float* __restrict__ bta, const float* __restrict__ W) {
    if (blockIdx.x < NODE_BLOCKS) {
        const int wid = threadIdx.x >> 5, lane = threadIdx.x & 31;
        const int node = blockIdx.x * 8 + wid;
        if (node >= N_NODES) return;
        float4 v = *(const float4*)(x + (size_t)node * FD + lane * 4);
        float s = v.x + v.y + v.z + v.w;
        float q = v.x * v.x + v.y * v.y + v.z * v.z + v.w * v.w;
#pragma unroll
        for (int o = 16; o; o >>= 1) {
            s += __shfl_xor_sync(~0u, s, o);
            q += __shfl_xor_sync(~0u, q, o);
        }
        const float mu = s * (1.f / FD), var = q * (1.f / FD) - mu * mu;
        const float rs = rsqrtf(var + 1e-5f);
        float4 g = *(const float4*)(gma + lane * 4);
        float4 b = *(const float4*)(bta + lane * 4);
        union { __half2 h[2]; uint2 u; } o;
        o.h[0] = __floats2half2_rn((v.x - mu) * rs * g.x + b.x, (v.y - mu) * rs * g.y + b.y);
        o.h[1] = __floats2half2_rn((v.z - mu) * rs * g.z + b.z, (v.w - mu) * rs * g.w + b.w);
        *(uint2*)(g_xn16 + (size_t)node * FD + lane * 4) = o.u;
    } else {
        // W -> Wt blocks, 32-col strips: [delta f..f+15 | gate f..f+15], f = strip*16
        const int n = blockIdx.x - NODE_BLOCKS;   // permuted col 0..255
        const int t = threadIdx.x;
        if (t >= KDIM / 8) return;
        const int strip = n >> 5, j = n & 31;
        const int f = strip * 16 + (j & 15);
        const int src = (j < 16) ? f : (128 + f);
        const int k0 = t * 8;
        const int kb = k0 >> 6, kl = k0 & 63;
        union { __half h[8]; uint4 u; } pk;
#pragma unroll
        for (int i = 0; i < 8; i++) pk.h[i] = __float2half_rn(W[(k0 + i) * NOUT + src]);
        const uint32_t phys = kb * 32768 + n * 128 + ((((kl >> 3) ^ (n & 7))) << 4);
        *(uint4*)(g_wt16 + phys) = pk.u;
    }
}

// =====================================================================
// fused edge kernel — three 8-warp groups (768 thr), 32x32 warp tiles,
// software-pipelined fragments inside each MMA phase
// =====================================================================
__global__ void __launch_bounds__(768, 1)
edge_kernel(const int* __restrict__ ei, const float* __restrict__ ea,
            const float* __restrict__ bias, const float* __restrict__ eg,
            const float* __restrict__ eb, float* __restrict__ out) {
    extern __shared__ char smem[];
    const uint32_t sm_u = smem_u32(smem);
    const uint32_t bB = sm_u + B_OFF;

    const int tid  = threadIdx.x;
    const int g    = tid >> 8;            // group 0..2
    const int ltid = tid & 255;
    const int wc8  = ltid >> 5;           // 0..7 : 32-col strip
    const int lane = ltid & 31;
    const int row8 = ltid >> 3, q8 = ltid & 7;   // A build: 32 rows x 8 thr
    const int r7 = row8 & 7;
    const int lq = lane & 3, lr = lane >> 2;

    const uint32_t bA = sm_u + A_OFF + g * A_G_STRIDE;
    int*   s_src = (int*)(smem + IDX_OFF) + g * 64;
    int*   s_dst = s_src + 32;
    float* psum  = (float*)(smem + PSUM_OFF) + g * 64;

    // ---- stage resident B ----
    {
        const uint4* src = (const uint4*)g_wt16;
        uint4* dst = (uint4*)(smem + B_OFF);
        for (int i = tid; i < B_BYTES / 16; i += 768) dst[i] = src[i];
    }

    // ---- ldmatrix lane addressing ----
    const int li = lane & 7, lgrp = lane >> 3;
    uint32_t a_off[2]; int a_r7[2];
#pragma unroll
    for (int s = 0; s < 2; s++) {
        const int row = s * 16 + li + (lgrp & 1) * 8;
        a_off[s] = row * 128;
        a_r7[s] = row & 7;
    }
    const int a_qb = lgrp >> 1;
    uint32_t b_off[2]; int b_r7[2];
#pragma unroll
    for (int j = 0; j < 2; j++) {
        const int rn = wc8 * 32 + j * 16 + li + (lgrp >> 1) * 8;
        b_off[j] = rn * 128;
        b_r7[j] = rn & 7;
    }
    const int b_qb = lgrp & 1;

    const uint32_t d_off = row8 * 128 + ((q8 ^ r7) << 4);
    const uint32_t res_base = bA + (wc8 >> 2) * A_BUF_G;

    __syncthreads();

    const int t0 = blockIdx.x * NGROUP + g;
    const int tstride = gridDim.x * NGROUP;

    float acc[2][4][4];
    float4 ea_st[2];

    // software-pipelined MMA phase: load ks+1 frags before issuing ks MMAs
    auto MMAPH = [&](int c) {
        const uint32_t abuf = bA + (c & 1) * A_BUF_G;
        const uint32_t bblk = bB + c * 32768;
        uint32_t A[2][2][4], Bv[2][2][4];
        // prologue: ks=0 fragments
#pragma unroll
        for (int s = 0; s < 2; s++)
            ldsm4(A[0][s], abuf + a_off[s] + (((a_qb ^ a_r7[s])) << 4));
#pragma unroll
        for (int j = 0; j < 2; j++)
            ldsm4(Bv[0][j], bblk + b_off[j] + (((b_qb ^ b_r7[j])) << 4));
#pragma unroll
        for (int ks = 0; ks < 4; ks++) {
            const int cur = ks & 1, nxt = cur ^ 1;
            if (ks < 3) {
#pragma unroll
                for (int s = 0; s < 2; s++)
                    ldsm4(A[nxt][s], abuf + a_off[s] + ((((2 * (ks + 1) + a_qb) ^ a_r7[s])) << 4));
#pragma unroll
                for (int j = 0; j < 2; j++)
                    ldsm4(Bv[nxt][j], bblk + b_off[j] + ((((2 * (ks + 1) + b_qb) ^ b_r7[j])) << 4));
            }
#pragma unroll
            for (int s = 0; s < 2; s++)
#pragma unroll
                for (int j = 0; j < 2; j++) {
                    mma16816(acc[s][2 * j],     A[cur][s], Bv[cur][j][0], Bv[cur][j][1]);
                    mma16816(acc[s][2 * j + 1], A[cur][s], Bv[cur][j][2], Bv[cur][j][3]);
                }
        }
    };
    auto SRC_GATHER = [&]() {
        const char* gp = (const char*)(g_xn16 + (size_t)s_src[row8] * FD) + q8 * 16;
        cpa16(bA + d_off, gp);
        cpa16(bA + A_BUF_G + d_off, gp + 128);
        CP_COMMIT();
    };

    // ---- group prologue ----
    if (t0 < NT_G) {
        const int tb0 = t0 * TILE_G;
        if (ltid < 32)       s_src[ltid] = ei[tb0 + ltid];
        else if (ltid < 64)  s_dst[ltid - 32] = ei[N_EDGES + tb0 + ltid - 32];
        else if (ltid >= 192) psum[ltid - 192] = 0.f;
    }
    GBAR(g);
    if (t0 < NT_G) SRC_GATHER();

    for (int t = t0; t < NT_G; t += tstride) {
        const int tb = t * TILE_G;
        const int er = tb + row8;
        const bool more = (t + tstride) < NT_G;

#pragma unroll
        for (int s = 0; s < 2; s++)
#pragma unroll
            for (int n = 0; n < 4; n++)
#pragma unroll
                for (int i = 0; i < 4; i++) acc[s][n][i] = 0.f;

        // ---- c0: src feats 0-63 (b0) ----
        CP_WAIT0();
        GBAR(g);
        if (ltid >= 192) psum[ltid - 192] = 0.f;
        MMAPH(0);

        // ---- c1: src feats 64-127 (b1); prefetch dst_lo -> b0 ----
        GBAR(g);
        {
            const char* gp = (const char*)(g_xn16 + (size_t)s_dst[row8] * FD) + q8 * 16;
            cpa16(bA + d_off, gp);
            CP_COMMIT();
        }
        MMAPH(1);

        // ---- c2: dst feats 0-63 (b0); prefetch dst_hi -> b1; LDG ea_lo ----
        CP_WAIT0();
        GBAR(g);
        {
            const char* gp = (const char*)(g_xn16 + (size_t)s_dst[row8] * FD + 64) + q8 * 16;
            cpa16(bA + A_BUF_G + d_off, gp);
            CP_COMMIT();
        }
        {
            const float* p = ea + (size_t)er * FD + q8 * 8;
            ea_st[0] = ldg_cs4(p);
            ea_st[1] = ldg_cs4(p + 4);
        }
        MMAPH(2);

        // ---- c3: dst feats 64-127 (b1); STS ea_lo -> b0; idx; LDG ea_hi ----
        CP_WAIT0();
        GBAR(g);
        sts16(bA + d_off, pack8h(ea_st[0], ea_st[1]));
        if (more) {
            const int tbn = (t + tstride) * TILE_G;
            if (ltid < 32)      s_src[ltid] = ei[tbn + ltid];
            else if (ltid < 64) s_dst[ltid - 32] = ei[N_EDGES + tbn + ltid - 32];
        }
        {
            const float* p = ea + (size_t)er * FD + 64 + q8 * 8;
            ea_st[0] = ldg_cs4(p);
            ea_st[1] = ldg_cs4(p + 4);
        }
        MMAPH(3);

        // ---- c4: ea feats 0-63 (b0); STS ea_hi -> b1 ----
        GBAR(g);
        sts16(bA + A_BUF_G + d_off, pack8h(ea_st[0], ea_st[1]));
        MMAPH(4);

        // ---- c5: ea feats 64-127 (b1) ----
        GBAR(g);
        MMAPH(5);
        // b0 = ea feats 0-63 (f16), b1 = feats 64-127 — residual source.

        // ---- epilogue part 1: gated residual (residual via LDS) + partials ----
        {
            float srs[4], qrs[4];
#pragma unroll
            for (int ri = 0; ri < 4; ri++) { srs[ri] = 0.f; qrs[ri] = 0.f; }

#pragma unroll
            for (int n = 0; n < 2; n++) {
                const int f = wc8 * 16 + n * 8 + lq * 2;
                const float2 bd = __ldg((const float2*)(bias + f));
                const float2 bg = __ldg((const float2*)(bias + 128 + f));
                const uint32_t colb = (wc8 & 3) * 32 + n * 16 + lq * 4;
                const uint32_t unit = colb >> 4;
#pragma unroll
                for (int s = 0; s < 2; s++)
#pragma unroll
                    for (int rh = 0; rh < 2; rh++) {
                        const int ri = s * 2 + rh;
                        const int row = s * 16 + rh * 8 + lr;
                        uint32_t ru;
                        asm volatile("ld.shared.b32 %0, [%1];"
                                     : "=r"(ru)
                                     : "r"(res_base + row * 128 + ((unit ^ (uint32_t)lr) << 4) + (colb & 15)));
                        const float2 res = __half22float2(*(__half2*)&ru);
                        float d0 = fmaxf(acc[s][n][rh * 2 + 0] + bd.x, 0.f);
                        float d1 = fmaxf(acc[s][n][rh * 2 + 1] + bd.y, 0.f);
                        float g0 = fmaxf(acc[s][n + 2][rh * 2 + 0] + bg.x, 0.f);
                        float g1 = fmaxf(acc[s][n + 2][rh * 2 + 1] + bg.y, 0.f);
                        float s0 = __frcp_rn(1.f + __expf(-g0));
                        float s1 = __frcp_rn(1.f + __expf(-g1));
                        float v0 = fmaf(d0, s0, res.x);
                        float v1 = fmaf(d1, s1, res.y);
                        acc[s][n][rh * 2 + 0] = v0;
                        acc[s][n][rh * 2 + 1] = v1;
                        srs[ri] += v0 + v1;
                        qrs[ri] = fmaf(v0, v0, fmaf(v1, v1, qrs[ri]));
                    }
            }
#pragma unroll
            for (int ri = 0; ri < 4; ri++) {
                float s_ = srs[ri], q_ = qrs[ri];
                s_ += __shfl_xor_sync(~0u, s_, 1);
                q_ += __shfl_xor_sync(~0u, q_, 1);
                s_ += __shfl_xor_sync(~0u, s_, 2);
                q_ += __shfl_xor_sync(~0u, q_, 2);
                if (lq == 0) {
                    const int row = (ri >> 1) * 16 + (ri & 1) * 8 + lr;
                    atomicAdd(&psum[row * 2],     s_);
                    atomicAdd(&psum[row * 2 + 1], q_);
                }
            }
        }
        GBAR(g);

        // ---- overlap: next tile's full src-row gather ----
        if (more) SRC_GATHER();

        // ---- epilogue part 2: LayerNorm + streaming store ----
        {
#pragma unroll
            for (int s = 0; s < 2; s++)
#pragma unroll
                for (int rh = 0; rh < 2; rh++) {
                    const int row = s * 16 + rh * 8 + lr;
                    const int e = tb + row;
                    const float2 p = *(const float2*)(psum + row * 2);
                    const float mu = p.x * (1.f / FD);
                    const float var = p.y * (1.f / FD) - mu * mu;
                    const float rs = rsqrtf(var + 1e-5f);
#pragma unroll
                    for (int n = 0; n < 2; n++) {
                        const int f = wc8 * 16 + n * 8 + lq * 2;
                        const float2 gg = __ldg((const float2*)(eg + f));
                        const float2 bb = __ldg((const float2*)(eb + f));
                        float2 o;
                        o.x = (acc[s][n][rh * 2 + 0] - mu) * rs * gg.x + bb.x;
                        o.y = (acc[s][n][rh * 2 + 1] - mu) * rs * gg.y + bb.y;
                        stg_cs2(out + (size_t)e * FD + f, o);
                    }
                }
        }
        // next tile's c0 GBAR orders psum reads before re-zero/atomics.
    }
}

// =====================================================================
// launch
// =====================================================================
extern "C" void kernel_launch(void* const* d_in, const int* in_sizes, int n_in,
                              void* d_out, int out_size) {
    const float* x  = (const float*)d_in[0];
    const int*   ei = (const int*)d_in[1];
    const float* ea = (const float*)d_in[2];
    const float* W  = (const float*)d_in[3];
    const float* b  = (const float*)d_in[4];
    const float* ng = (const float*)d_in[5];
    const float* nb = (const float*)d_in[6];
    const float* eg = (const float*)d_in[7];
    const float* eb = (const float*)d_in[8];
    float* out = (float*)d_out;

    prep_kernel<<<NODE_BLOCKS + NOUT, 256>>>(x, ng, nb, W);

    cudaFuncSetAttribute(edge_kernel, cudaFuncAttributeMaxDynamicSharedMemorySize, SMEM_TOTAL);
    int nsm = 148;
    cudaDeviceGetAttribute(&nsm, cudaDevAttrMultiProcessorCount, 0);
    edge_kernel<<<nsm, 768, SMEM_TOTAL>>>(ei, ea, b, eg, eb, out);
}